// round 6
// baseline (speedup 1.0000x reference)
#include <cuda_runtime.h>
#include <math.h>

// Problem constants
#define BVAL 2
#define TVAL 1024
#define SVAL 2048
#define DVAL 1024
#define HVAL 16
#define HDVAL 64

typedef unsigned long long u64;

// Scratch (no allocations allowed — __device__ globals, referenced directly)
__device__ float g_Q[BVAL * TVAL * DVAL];     // 8 MB
__device__ float g_K[BVAL * SVAL * DVAL];     // 16 MB
__device__ float g_V[BVAL * SVAL * DVAL];     // 16 MB
__device__ float g_ATT[BVAL * TVAL * DVAL];   // 8 MB
__device__ float g_O[BVAL * TVAL * DVAL];     // 8 MB

// ---------------------------------------------------------------------------
// Packed f32x2 helpers (Blackwell: FFMA2 only reachable via PTX fma.rn.f32x2)
// Exact fp32 semantics per lane — no precision change vs scalar FFMA.
// ---------------------------------------------------------------------------
__device__ __forceinline__ u64 dup2(float x) {
    u64 r; unsigned xi = __float_as_uint(x);
    asm("mov.b64 %0, {%1, %1};" : "=l"(r) : "r"(xi));
    return r;
}
__device__ __forceinline__ void fma2(u64& d, u64 a, u64 b) {
    asm("fma.rn.f32x2 %0, %1, %2, %3;" : "=l"(d) : "l"(a), "l"(b), "l"(d));
}
__device__ __forceinline__ void mul2(u64& d, u64 a, u64 b) {
    asm("mul.rn.f32x2 %0, %1, %2;" : "=l"(d) : "l"(a), "l"(b));
}
__device__ __forceinline__ float2 unpack2(u64 v) {
    unsigned lo, hi;
    asm("mov.b64 {%0, %1}, %2;" : "=r"(lo), "=r"(hi) : "l"(v));
    return make_float2(__uint_as_float(lo), __uint_as_float(hi));
}

// ---------------------------------------------------------------------------
// GEMM body (NT): C[M,N] = A[M,K] * W[N,K]^T, K-major rows on both sides.
// 128x128 tile, BK=16, 256 threads, 8x8 microtile (stored as 8x4 f32x2 pairs).
// Double-buffered smem (1 barrier/iter) + register prefetch.
// ---------------------------------------------------------------------------
#define BMT 128
#define BNT 128
#define BKT 16

__device__ __forceinline__ void gemm_body(const float* __restrict__ A,
                                          const float* __restrict__ W,
                                          float* __restrict__ C,
                                          int K, int N, int bm, int bn,
                                          float As[2][BKT][BMT],
                                          float Ws[2][BKT][BNT]) {
    const int tid = threadIdx.x;
    const int tx = tid & 15;        // N direction
    const int ty = tid >> 4;        // M direction

    u64 acc2[8][4];                 // [m][n-pair], lane.lo = even col
#pragma unroll
    for (int i = 0; i < 8; i++)
#pragma unroll
        for (int j = 0; j < 4; j++) acc2[i][j] = 0ull;

    const int lrow = tid >> 2;          // 0..63
    const int lcol = (tid & 3) * 4;     // 0,4,8,12

    // ---- load first tile into buffer 0 ----
#pragma unroll
    for (int half = 0; half < 2; half++) {
        int m = lrow + half * 64;
        float4 a = *(const float4*)&A[(size_t)(bm + m) * K + lcol];
        As[0][lcol + 0][m] = a.x; As[0][lcol + 1][m] = a.y;
        As[0][lcol + 2][m] = a.z; As[0][lcol + 3][m] = a.w;
        float4 w = *(const float4*)&W[(size_t)(bn + m) * K + lcol];
        Ws[0][lcol + 0][m] = w.x; Ws[0][lcol + 1][m] = w.y;
        Ws[0][lcol + 2][m] = w.z; Ws[0][lcol + 3][m] = w.w;
    }
    __syncthreads();

    int cur = 0;
    for (int k0 = 0; k0 < K; k0 += BKT) {
        // ---- prefetch next tile into registers (overlaps compute) ----
        float4 pa[2], pw[2];
        const bool more = (k0 + BKT) < K;
        if (more) {
#pragma unroll
            for (int half = 0; half < 2; half++) {
                int m = lrow + half * 64;
                pa[half] = *(const float4*)&A[(size_t)(bm + m) * K + k0 + BKT + lcol];
                pw[half] = *(const float4*)&W[(size_t)(bn + m) * K + k0 + BKT + lcol];
            }
        }

        // ---- compute on current buffer: FFMA2 path ----
#pragma unroll
        for (int kk = 0; kk < BKT; kk++) {
            float af[8];
            *(float4*)&af[0] = *(const float4*)&As[cur][kk][ty * 8];
            *(float4*)&af[4] = *(const float4*)&As[cur][kk][ty * 8 + 4];
            // W pairs come free: reinterpret the 16B rows as 2x f32x2
            ulonglong2 w01 = *(const ulonglong2*)&Ws[cur][kk][tx * 8];
            ulonglong2 w23 = *(const ulonglong2*)&Ws[cur][kk][tx * 8 + 4];
            u64 wrow[4] = {w01.x, w01.y, w23.x, w23.y};
#pragma unroll
            for (int i = 0; i < 8; i++) {
                u64 a2 = dup2(af[i]);
#pragma unroll
                for (int j = 0; j < 4; j++) fma2(acc2[i][j], a2, wrow[j]);
            }
        }

        if (more) {
            int nxt = cur ^ 1;      // opposite buffer: no WAR barrier needed
#pragma unroll
            for (int half = 0; half < 2; half++) {
                int m = lrow + half * 64;
                As[nxt][lcol + 0][m] = pa[half].x; As[nxt][lcol + 1][m] = pa[half].y;
                As[nxt][lcol + 2][m] = pa[half].z; As[nxt][lcol + 3][m] = pa[half].w;
                Ws[nxt][lcol + 0][m] = pw[half].x; Ws[nxt][lcol + 1][m] = pw[half].y;
                Ws[nxt][lcol + 2][m] = pw[half].z; Ws[nxt][lcol + 3][m] = pw[half].w;
            }
            __syncthreads();
            cur = nxt;
        }
    }

#pragma unroll
    for (int i = 0; i < 8; i++) {
        float2 c0 = unpack2(acc2[i][0]);
        float2 c1 = unpack2(acc2[i][1]);
        float2 c2 = unpack2(acc2[i][2]);
        float2 c3 = unpack2(acc2[i][3]);
        float4* dst = (float4*)&C[(size_t)(bm + ty * 8 + i) * N + bn + tx * 8];
        dst[0] = make_float4(c0.x, c0.y, c1.x, c1.y);
        dst[1] = make_float4(c2.x, c2.y, c3.x, c3.y);
    }
}

// ---------------------------------------------------------------------------
// Merged Q/K/V projection: blockIdx.z selects {0:Q, 1:K, 2:V}.
// One launch (640 productive blocks) amortizes wave-quantization tails.
// ---------------------------------------------------------------------------
__global__ __launch_bounds__(256) void qkv_gemm(const float* __restrict__ query,
                                                const float* __restrict__ context,
                                                const float* __restrict__ Wq,
                                                const float* __restrict__ Wk,
                                                const float* __restrict__ Wv) {
    __shared__ float As[2][BKT][BMT];
    __shared__ float Ws[2][BKT][BNT];

    const int z = blockIdx.z;
    const int M = (z == 0) ? (BVAL * TVAL) : (BVAL * SVAL);
    const int bm = blockIdx.y * BMT;
    if (bm >= M) return;                      // idle tail blocks for z==0
    const int bn = blockIdx.x * BNT;

    const float* A = (z == 0) ? query : context;
    const float* W = (z == 0) ? Wq : (z == 1) ? Wk : Wv;
    float* C       = (z == 0) ? g_Q : (z == 1) ? g_K : g_V;

    gemm_body(A, W, C, DVAL, DVAL, bm, bn, As, Ws);
}

// Output projection: g_O = g_ATT @ Wo^T
__global__ __launch_bounds__(256) void o_gemm(const float* __restrict__ Wo) {
    __shared__ float As[2][BKT][BMT];
    __shared__ float Ws[2][BKT][BNT];
    gemm_body(g_ATT, Wo, g_O, DVAL, DVAL, blockIdx.y * BMT, blockIdx.x * BNT, As, Ws);
}

// ---------------------------------------------------------------------------
// Flash-style attention with ALiBi bias, packed-f32x2 math.
// Grid: (T/64, H, B). Block: 64 threads, one query row per thread.
// q (32 pairs) and acc (32 pairs) live in registers; K/V tiles (64 keys)
// broadcast from SMEM. Scores: both operands are natural pairs -> pure FFMA2.
// PV: one dup(p) per key. Scores staged transposed (Ss[j][tid]) = conflict-
// free without padding; total static smem exactly 48 KB.
// ---------------------------------------------------------------------------
__global__ __launch_bounds__(64) void attn_kernel() {
    const int TS = 64;
    __shared__ float Ks[TS][HDVAL];    // 16384 B
    __shared__ float Vs[TS][HDVAL];    // 16384 B
    __shared__ float Ss[TS][64];       // 16384 B

    const int tid = threadIdx.x;
    const int b = blockIdx.z;
    const int h = blockIdx.y;
    const int t = blockIdx.x * 64 + tid;
    const float slope = exp2f(-(float)(h + 1) / (float)HVAL);
    const float scale = 0.125f;        // 64^-0.5

    u64 q2[HDVAL / 2];
    {
        const float* qp = &g_Q[((size_t)(b * TVAL + t)) * DVAL + h * HDVAL];
        const u64* qp64 = (const u64*)qp;   // 8B-aligned (offset multiple of 256B)
#pragma unroll
        for (int i = 0; i < HDVAL / 2; i++) q2[i] = qp64[i];
    }

    u64 acc2[HDVAL / 2];
#pragma unroll
    for (int i = 0; i < HDVAL / 2; i++) acc2[i] = 0ull;
    float mval = -1e30f, lval = 0.f;

    for (int s0 = 0; s0 < SVAL; s0 += TS) {
        __syncthreads();
        // cooperative tile load: TS*HD = 4096 floats each, 16x float4 per thread
#pragma unroll
        for (int i = 0; i < (TS * HDVAL) / (64 * 4); i++) {
            int idx = (tid + i * 64) * 4;
            int j = idx / HDVAL, d = idx % HDVAL;
            size_t gbase = ((size_t)(b * SVAL + s0 + j)) * DVAL + h * HDVAL + d;
            *(float4*)&Ks[j][d] = *(const float4*)&g_K[gbase];
            *(float4*)&Vs[j][d] = *(const float4*)&g_V[gbase];
        }
        __syncthreads();

        // scores: 2 packed accumulators = 4 independent scalar chains
        float tmax = -1e30f;
        for (int j = 0; j < TS; j++) {
            u64 sa = 0ull, sb = 0ull;
            const ulonglong2* krow = (const ulonglong2*)&Ks[j][0];
#pragma unroll
            for (int d2 = 0; d2 < HDVAL / 4; d2++) {
                ulonglong2 kv = krow[d2];
                fma2(sa, q2[2 * d2 + 0], kv.x);
                fma2(sb, q2[2 * d2 + 1], kv.y);
            }
            float2 fa = unpack2(sa), fb = unpack2(sb);
            float s = (fa.x + fa.y) + (fb.x + fb.y);
            s = s * scale - slope * fabsf((float)(t - (s0 + j)));
            Ss[j][tid] = s;
            tmax = fmaxf(tmax, s);
        }

        // online softmax rescale (packed)
        float nm = fmaxf(mval, tmax);
        float f = __expf(mval - nm);
        mval = nm;
        lval *= f;
        u64 f2 = dup2(f);
#pragma unroll
        for (int i = 0; i < HDVAL / 2; i++) mul2(acc2[i], acc2[i], f2);

        // probability-weighted V accumulation (packed, 32 independent chains)
        for (int j = 0; j < TS; j++) {
            float p = __expf(Ss[j][tid] - nm);
            lval += p;
            u64 p2 = dup2(p);
            const ulonglong2* vrow = (const ulonglong2*)&Vs[j][0];
#pragma unroll
            for (int d2 = 0; d2 < HDVAL / 4; d2++) {
                ulonglong2 vv = vrow[d2];
                fma2(acc2[2 * d2 + 0], p2, vv.x);
                fma2(acc2[2 * d2 + 1], p2, vv.y);
            }
        }
    }

    float inv = 1.f / lval;
    float* op = &g_ATT[((size_t)(b * TVAL + t)) * DVAL + h * HDVAL];
#pragma unroll
    for (int d2 = 0; d2 < HDVAL / 4; d2++) {
        float2 e = unpack2(acc2[2 * d2 + 0]);
        float2 o = unpack2(acc2[2 * d2 + 1]);
        *(float4*)&op[d2 * 4] =
            make_float4(e.x * inv, e.y * inv, o.x * inv, o.y * inv);
    }
}

// ---------------------------------------------------------------------------
// Fused residual + RMSNorm: out = rmsnorm(query + O) * w
// One block per row (B*T rows), 256 threads, 4 elems per thread.
// ---------------------------------------------------------------------------
__global__ __launch_bounds__(256) void rmsnorm_kernel(const float* __restrict__ X,
                                                      const float* __restrict__ w,
                                                      float* __restrict__ out) {
    const int row = blockIdx.x;
    const int base = threadIdx.x * 4;
    const float* xp = &X[(size_t)row * DVAL];
    const float* op = &g_O[(size_t)row * DVAL];

    float4 xv = *(const float4*)&xp[base];
    float4 ov = *(const float4*)&op[base];
    float v0 = xv.x + ov.x, v1 = xv.y + ov.y, v2 = xv.z + ov.z, v3 = xv.w + ov.w;
    float ss = v0 * v0 + v1 * v1 + v2 * v2 + v3 * v3;

#pragma unroll
    for (int o = 16; o > 0; o >>= 1) ss += __shfl_xor_sync(0xffffffffu, ss, o);

    __shared__ float red[8];
    if ((threadIdx.x & 31) == 0) red[threadIdx.x >> 5] = ss;
    __syncthreads();
    float tot = 0.f;
#pragma unroll
    for (int i = 0; i < 8; i++) tot += red[i];

    float inv = rsqrtf(tot * (1.0f / DVAL) + 1e-6f);
    float4 wv = *(const float4*)&w[base];
    *(float4*)&out[(size_t)row * DVAL + base] =
        make_float4(v0 * inv * wv.x, v1 * inv * wv.y, v2 * inv * wv.z, v3 * inv * wv.w);
}

// ---------------------------------------------------------------------------
extern "C" void kernel_launch(void* const* d_in, const int* in_sizes, int n_in,
                              void* d_out, int out_size) {
    const float* query   = (const float*)d_in[0];
    const float* context = (const float*)d_in[1];
    const float* Wq      = (const float*)d_in[2];
    const float* Wk      = (const float*)d_in[3];
    const float* Wv      = (const float*)d_in[4];
    const float* Wo      = (const float*)d_in[5];
    const float* rmsw    = (const float*)d_in[6];
    float* out           = (float*)d_out;

    const int MQ = BVAL * TVAL;   // 2048
    const int MK = BVAL * SVAL;   // 4096

    // Merged Q/K/V projection: grid (N/128, maxM/128, 3); z==0 tail blocks idle.
    dim3 gqkv(DVAL / BNT, MK / BMT, 3);   // 8 x 32 x 3
    qkv_gemm<<<gqkv, 256>>>(query, context, Wq, Wk, Wv);

    dim3 ga(TVAL / 64, HVAL, BVAL);       // 16 x 16 x 2
    attn_kernel<<<ga, 64>>>();

    dim3 go(DVAL / BNT, MQ / BMT);        // 8 x 16
    o_gemm<<<go, 256>>>(Wo);

    rmsnorm_kernel<<<BVAL * TVAL, 256>>>(query, rmsw, out);
}

// round 9
// speedup vs baseline: 1.4009x; 1.4009x over previous
#include <cuda_runtime.h>
#include <math.h>
#include <stdint.h>

// Problem constants
#define BVAL 2
#define TVAL 1024
#define SVAL 2048
#define DVAL 1024
#define HVAL 16
#define HDVAL 64

typedef unsigned long long u64;

// Scratch (no allocations allowed — __device__ globals, referenced directly)
__device__ float g_Q[BVAL * TVAL * DVAL];     // 8 MB
__device__ float g_K[BVAL * SVAL * DVAL];     // 16 MB
__device__ float g_V[BVAL * SVAL * DVAL];     // 16 MB
__device__ float g_ATT[BVAL * TVAL * DVAL];   // 8 MB
__device__ float g_O[BVAL * TVAL * DVAL];     // 8 MB

// ---------------------------------------------------------------------------
// Packed f32x2 helpers (attention path — exact fp32, unchanged from R6 pass)
// ---------------------------------------------------------------------------
__device__ __forceinline__ u64 dup2(float x) {
    u64 r; unsigned xi = __float_as_uint(x);
    asm("mov.b64 %0, {%1, %1};" : "=l"(r) : "r"(xi));
    return r;
}
__device__ __forceinline__ void fma2(u64& d, u64 a, u64 b) {
    asm("fma.rn.f32x2 %0, %1, %2, %3;" : "=l"(d) : "l"(a), "l"(b), "l"(d));
}
__device__ __forceinline__ void mul2(u64& d, u64 a, u64 b) {
    asm("mul.rn.f32x2 %0, %1, %2;" : "=l"(d) : "l"(a), "l"(b));
}
__device__ __forceinline__ float2 unpack2(u64 v) {
    unsigned lo, hi;
    asm("mov.b64 {%0, %1}, %2;" : "=r"(lo), "=r"(hi) : "l"(v));
    return make_float2(__uint_as_float(lo), __uint_as_float(hi));
}

// ---------------------------------------------------------------------------
// tf32 helpers
// ---------------------------------------------------------------------------
__device__ __forceinline__ uint32_t f2tf32(float x) {
    uint32_t r;
    asm("cvt.rna.tf32.f32 %0, %1;" : "=r"(r) : "f"(x));
    return r;
}
__device__ __forceinline__ void mma_tf32(float c[4], const uint32_t a[4],
                                         const uint32_t b[2]) {
    asm("mma.sync.aligned.m16n8k8.row.col.f32.tf32.tf32.f32 "
        "{%0,%1,%2,%3},{%4,%5,%6,%7},{%8,%9},{%0,%1,%2,%3};"
        : "+f"(c[0]), "+f"(c[1]), "+f"(c[2]), "+f"(c[3])
        : "r"(a[0]), "r"(a[1]), "r"(a[2]), "r"(a[3]), "r"(b[0]), "r"(b[1]));
}

// ---------------------------------------------------------------------------
// Tensor-core GEMM (NT): C[M,N] = A[M,K] * W[N,K]^T, both K-major rows.
// Block 128x128, 8 warps (4m x 2n), warp tile 32x64, BK=16 (2 k8 steps).
// tf32 mma.sync m16n8k8, fp32 accumulate. Smem row stride 20 floats ->
// fragment LDS provably bank-conflict-free. Double-buffered, 1 barrier/stage.
// ---------------------------------------------------------------------------
#define BMT 128
#define BNT 128
#define BKT 16
#define LDT 20      // smem row stride in 32-bit words

__device__ __forceinline__ void gemm_body_tc(const float* __restrict__ A,
                                             const float* __restrict__ W,
                                             float* __restrict__ C,
                                             int K, int N, int bm, int bn,
                                             uint32_t* As, uint32_t* Ws) {
    // As/Ws: [2][128][LDT] word arrays (buf stride 128*LDT)
    const int tid = threadIdx.x;
    const int lane = tid & 31;
    const int wid = tid >> 5;
    const int warp_m = wid & 3;         // 0..3 -> 32-row slice
    const int warp_n = wid >> 2;        // 0..1 -> 64-col slice
    const int m_base = warp_m * 32;
    const int n_base = warp_n * 64;
    const int grp = lane >> 2;          // 0..7
    const int tig = lane & 3;           // 0..3

    float acc[2][8][4];
#pragma unroll
    for (int mi = 0; mi < 2; mi++)
#pragma unroll
        for (int ni = 0; ni < 8; ni++)
#pragma unroll
            for (int r = 0; r < 4; r++) acc[mi][ni][r] = 0.f;

    // loader: thread -> one row, 8 consecutive floats (2 float4)
    const int lrow = tid >> 1;              // 0..127
    const int lcb = (tid & 1) * 8;          // 0 or 8

    const size_t a_row_off = (size_t)(bm + lrow) * K + lcb;
    const size_t w_row_off = (size_t)(bn + lrow) * K + lcb;

    // ---- stage 0 load ----
    {
        float4 f0 = *(const float4*)&A[a_row_off];
        float4 f1 = *(const float4*)&A[a_row_off + 4];
        uint4 u0 = make_uint4(f2tf32(f0.x), f2tf32(f0.y), f2tf32(f0.z), f2tf32(f0.w));
        uint4 u1 = make_uint4(f2tf32(f1.x), f2tf32(f1.y), f2tf32(f1.z), f2tf32(f1.w));
        *(uint4*)&As[lrow * LDT + lcb] = u0;
        *(uint4*)&As[lrow * LDT + lcb + 4] = u1;
        float4 g0 = *(const float4*)&W[w_row_off];
        float4 g1 = *(const float4*)&W[w_row_off + 4];
        uint4 v0 = make_uint4(f2tf32(g0.x), f2tf32(g0.y), f2tf32(g0.z), f2tf32(g0.w));
        uint4 v1 = make_uint4(f2tf32(g1.x), f2tf32(g1.y), f2tf32(g1.z), f2tf32(g1.w));
        *(uint4*)&Ws[lrow * LDT + lcb] = v0;
        *(uint4*)&Ws[lrow * LDT + lcb + 4] = v1;
    }
    __syncthreads();

    const int BUF = 128 * LDT;
    int cur = 0;
    for (int k0 = 0; k0 < K; k0 += BKT) {
        // ---- prefetch next stage (global -> regs) ----
        float4 f0, f1, g0, g1;
        const bool more = (k0 + BKT) < K;
        if (more) {
            f0 = *(const float4*)&A[a_row_off + k0 + BKT];
            f1 = *(const float4*)&A[a_row_off + k0 + BKT + 4];
            g0 = *(const float4*)&W[w_row_off + k0 + BKT];
            g1 = *(const float4*)&W[w_row_off + k0 + BKT + 4];
        }

        // ---- compute: two k8 steps on current buffer ----
        const uint32_t* Ab = As + cur * BUF;
        const uint32_t* Wb = Ws + cur * BUF;
#pragma unroll
        for (int s = 0; s < 2; s++) {
            const int kc = s * 8 + tig;
            uint32_t afr[2][4];
#pragma unroll
            for (int mi = 0; mi < 2; mi++) {
                int r0 = m_base + mi * 16 + grp;
                afr[mi][0] = Ab[r0 * LDT + kc];
                afr[mi][1] = Ab[(r0 + 8) * LDT + kc];
                afr[mi][2] = Ab[r0 * LDT + kc + 4];
                afr[mi][3] = Ab[(r0 + 8) * LDT + kc + 4];
            }
            uint32_t bfr[8][2];
#pragma unroll
            for (int ni = 0; ni < 8; ni++) {
                int n0 = n_base + ni * 8 + grp;
                bfr[ni][0] = Wb[n0 * LDT + kc];
                bfr[ni][1] = Wb[n0 * LDT + kc + 4];
            }
#pragma unroll
            for (int mi = 0; mi < 2; mi++)
#pragma unroll
                for (int ni = 0; ni < 8; ni++)
                    mma_tf32(acc[mi][ni], afr[mi], bfr[ni]);
        }

        if (more) {
            int nxt = cur ^ 1;
            uint32_t* An = As + nxt * BUF;
            uint32_t* Wn = Ws + nxt * BUF;
            uint4 u0 = make_uint4(f2tf32(f0.x), f2tf32(f0.y), f2tf32(f0.z), f2tf32(f0.w));
            uint4 u1 = make_uint4(f2tf32(f1.x), f2tf32(f1.y), f2tf32(f1.z), f2tf32(f1.w));
            *(uint4*)&An[lrow * LDT + lcb] = u0;
            *(uint4*)&An[lrow * LDT + lcb + 4] = u1;
            uint4 v0 = make_uint4(f2tf32(g0.x), f2tf32(g0.y), f2tf32(g0.z), f2tf32(g0.w));
            uint4 v1 = make_uint4(f2tf32(g1.x), f2tf32(g1.y), f2tf32(g1.z), f2tf32(g1.w));
            *(uint4*)&Wn[lrow * LDT + lcb] = v0;
            *(uint4*)&Wn[lrow * LDT + lcb + 4] = v1;
            __syncthreads();
            cur = nxt;
        }
    }

    // ---- epilogue: c0/c1 at (grp, tig*2), c2/c3 at (grp+8, tig*2) ----
#pragma unroll
    for (int mi = 0; mi < 2; mi++) {
#pragma unroll
        for (int ni = 0; ni < 8; ni++) {
            int row = bm + m_base + mi * 16 + grp;
            int col = bn + n_base + ni * 8 + tig * 2;
            *(float2*)&C[(size_t)row * N + col] =
                make_float2(acc[mi][ni][0], acc[mi][ni][1]);
            *(float2*)&C[(size_t)(row + 8) * N + col] =
                make_float2(acc[mi][ni][2], acc[mi][ni][3]);
        }
    }
}

// ---------------------------------------------------------------------------
// Merged Q/K/V projection: blockIdx.z selects {0:Q, 1:K, 2:V}.
// ---------------------------------------------------------------------------
__global__ __launch_bounds__(256) void qkv_gemm(const float* __restrict__ query,
                                                const float* __restrict__ context,
                                                const float* __restrict__ Wq,
                                                const float* __restrict__ Wk,
                                                const float* __restrict__ Wv) {
    __shared__ uint32_t As[2 * 128 * LDT];
    __shared__ uint32_t Ws[2 * 128 * LDT];

    const int z = blockIdx.z;
    const int M = (z == 0) ? (BVAL * TVAL) : (BVAL * SVAL);
    const int bm = blockIdx.y * BMT;
    if (bm >= M) return;
    const int bn = blockIdx.x * BNT;

    const float* A = (z == 0) ? query : context;
    const float* W = (z == 0) ? Wq : (z == 1) ? Wk : Wv;
    float* C       = (z == 0) ? g_Q : (z == 1) ? g_K : g_V;

    gemm_body_tc(A, W, C, DVAL, DVAL, bm, bn, As, Ws);
}

// Output projection: g_O = g_ATT @ Wo^T
__global__ __launch_bounds__(256) void o_gemm(const float* __restrict__ Wo) {
    __shared__ uint32_t As[2 * 128 * LDT];
    __shared__ uint32_t Ws[2 * 128 * LDT];
    gemm_body_tc(g_ATT, Wo, g_O, DVAL, DVAL,
                 blockIdx.y * BMT, blockIdx.x * BNT, As, Ws);
}

// ---------------------------------------------------------------------------
// Flash-style attention with ALiBi bias, packed-f32x2 math.
// (unchanged from the R6 passing version, rel_err 2.35e-7)
// ---------------------------------------------------------------------------
__global__ __launch_bounds__(64) void attn_kernel() {
    const int TS = 64;
    __shared__ float Ks[TS][HDVAL];    // 16384 B
    __shared__ float Vs[TS][HDVAL];    // 16384 B
    __shared__ float Ss[TS][64];       // 16384 B

    const int tid = threadIdx.x;
    const int b = blockIdx.z;
    const int h = blockIdx.y;
    const int t = blockIdx.x * 64 + tid;
    const float slope = exp2f(-(float)(h + 1) / (float)HVAL);
    const float scale = 0.125f;        // 64^-0.5

    u64 q2[HDVAL / 2];
    {
        const float* qp = &g_Q[((size_t)(b * TVAL + t)) * DVAL + h * HDVAL];
        const u64* qp64 = (const u64*)qp;
#pragma unroll
        for (int i = 0; i < HDVAL / 2; i++) q2[i] = qp64[i];
    }

    u64 acc2[HDVAL / 2];
#pragma unroll
    for (int i = 0; i < HDVAL / 2; i++) acc2[i] = 0ull;
    float mval = -1e30f, lval = 0.f;

    for (int s0 = 0; s0 < SVAL; s0 += TS) {
        __syncthreads();
#pragma unroll
        for (int i = 0; i < (TS * HDVAL) / (64 * 4); i++) {
            int idx = (tid + i * 64) * 4;
            int j = idx / HDVAL, d = idx % HDVAL;
            size_t gbase = ((size_t)(b * SVAL + s0 + j)) * DVAL + h * HDVAL + d;
            *(float4*)&Ks[j][d] = *(const float4*)&g_K[gbase];
            *(float4*)&Vs[j][d] = *(const float4*)&g_V[gbase];
        }
        __syncthreads();

        float tmax = -1e30f;
        for (int j = 0; j < TS; j++) {
            u64 sa = 0ull, sb = 0ull;
            const ulonglong2* krow = (const ulonglong2*)&Ks[j][0];
#pragma unroll
            for (int d2 = 0; d2 < HDVAL / 4; d2++) {
                ulonglong2 kv = krow[d2];
                fma2(sa, q2[2 * d2 + 0], kv.x);
                fma2(sb, q2[2 * d2 + 1], kv.y);
            }
            float2 fa = unpack2(sa), fb = unpack2(sb);
            float s = (fa.x + fa.y) + (fb.x + fb.y);
            s = s * scale - slope * fabsf((float)(t - (s0 + j)));
            Ss[j][tid] = s;
            tmax = fmaxf(tmax, s);
        }

        float nm = fmaxf(mval, tmax);
        float f = __expf(mval - nm);
        mval = nm;
        lval *= f;
        u64 f2 = dup2(f);
#pragma unroll
        for (int i = 0; i < HDVAL / 2; i++) mul2(acc2[i], acc2[i], f2);

        for (int j = 0; j < TS; j++) {
            float p = __expf(Ss[j][tid] - nm);
            lval += p;
            u64 p2 = dup2(p);
            const ulonglong2* vrow = (const ulonglong2*)&Vs[j][0];
#pragma unroll
            for (int d2 = 0; d2 < HDVAL / 4; d2++) {
                ulonglong2 vv = vrow[d2];
                fma2(acc2[2 * d2 + 0], p2, vv.x);
                fma2(acc2[2 * d2 + 1], p2, vv.y);
            }
        }
    }

    float inv = 1.f / lval;
    float* op = &g_ATT[((size_t)(b * TVAL + t)) * DVAL + h * HDVAL];
#pragma unroll
    for (int d2 = 0; d2 < HDVAL / 4; d2++) {
        float2 e = unpack2(acc2[2 * d2 + 0]);
        float2 o = unpack2(acc2[2 * d2 + 1]);
        *(float4*)&op[d2 * 4] =
            make_float4(e.x * inv, e.y * inv, o.x * inv, o.y * inv);
    }
}

// ---------------------------------------------------------------------------
// Fused residual + RMSNorm (unchanged)
// ---------------------------------------------------------------------------
__global__ __launch_bounds__(256) void rmsnorm_kernel(const float* __restrict__ X,
                                                      const float* __restrict__ w,
                                                      float* __restrict__ out) {
    const int row = blockIdx.x;
    const int base = threadIdx.x * 4;
    const float* xp = &X[(size_t)row * DVAL];
    const float* op = &g_O[(size_t)row * DVAL];

    float4 xv = *(const float4*)&xp[base];
    float4 ov = *(const float4*)&op[base];
    float v0 = xv.x + ov.x, v1 = xv.y + ov.y, v2 = xv.z + ov.z, v3 = xv.w + ov.w;
    float ss = v0 * v0 + v1 * v1 + v2 * v2 + v3 * v3;

#pragma unroll
    for (int o = 16; o > 0; o >>= 1) ss += __shfl_xor_sync(0xffffffffu, ss, o);

    __shared__ float red[8];
    if ((threadIdx.x & 31) == 0) red[threadIdx.x >> 5] = ss;
    __syncthreads();
    float tot = 0.f;
#pragma unroll
    for (int i = 0; i < 8; i++) tot += red[i];

    float inv = rsqrtf(tot * (1.0f / DVAL) + 1e-6f);
    float4 wv = *(const float4*)&w[base];
    *(float4*)&out[(size_t)row * DVAL + base] =
        make_float4(v0 * inv * wv.x, v1 * inv * wv.y, v2 * inv * wv.z, v3 * inv * wv.w);
}

// ---------------------------------------------------------------------------
extern "C" void kernel_launch(void* const* d_in, const int* in_sizes, int n_in,
                              void* d_out, int out_size) {
    const float* query   = (const float*)d_in[0];
    const float* context = (const float*)d_in[1];
    const float* Wq      = (const float*)d_in[2];
    const float* Wk      = (const float*)d_in[3];
    const float* Wv      = (const float*)d_in[4];
    const float* Wo      = (const float*)d_in[5];
    const float* rmsw    = (const float*)d_in[6];
    float* out           = (float*)d_out;

    const int MQ = BVAL * TVAL;   // 2048
    const int MK = BVAL * SVAL;   // 4096

    dim3 gqkv(DVAL / BNT, MK / BMT, 3);   // 8 x 32 x 3
    qkv_gemm<<<gqkv, 256>>>(query, context, Wq, Wk, Wv);

    dim3 ga(TVAL / 64, HVAL, BVAL);       // 16 x 16 x 2
    attn_kernel<<<ga, 64>>>();

    dim3 go(DVAL / BNT, MQ / BMT);        // 8 x 16
    o_gemm<<<go, 256>>>(Wo);

    rmsnorm_kernel<<<BVAL * TVAL, 256>>>(query, rmsw, out);
}